// round 2
// baseline (speedup 1.0000x reference)
#include <cuda_runtime.h>

// Depthwise Conv1d: B=32, C=128, L=8192, kernel=3, stride=1, pad=1, fp32.
// out[b,c,l] = w[c,0]*x[b,c,l-1] + w[c,1]*x[b,c,l] + w[c,2]*x[b,c,l+1] + bias[c]
//
// R2: ILP=4 — each thread processes 4 consecutive float4 (16 outputs, 64B),
// front-batched loads for MLP, streaming cache hints. Halo = 2 scalar loads
// per thread (amortized over 64B instead of 16B).

#define BATCH 32
#define CHANS 128
#define LEN   8192
#define LEN4  (LEN / 4)            // 2048 float4 per row
#define ROWS  (BATCH * CHANS)      // 4096
#define ILP   4                    // float4 per thread
#define TILES_PER_ROW (LEN4 / ILP) // 512
#define NTHREADS 256

__global__ __launch_bounds__(NTHREADS)
void dwconv1d_kernel(const float* __restrict__ x,
                     const float* __restrict__ w,
                     const float* __restrict__ bias,
                     float* __restrict__ out)
{
    unsigned int gid = blockIdx.x * NTHREADS + threadIdx.x;

    unsigned int row = gid >> 9;                     // / TILES_PER_ROW
    unsigned int t   = gid & (TILES_PER_ROW - 1);    // tile index within row
    unsigned int j   = t * ILP;                      // first float4 index
    unsigned int c   = row & (CHANS - 1);

    const float4* xrow = reinterpret_cast<const float4*>(x) + (size_t)row * LEN4;
    const float*  xs   = reinterpret_cast<const float*>(xrow);

    // ---- front-batched loads (high MLP) ----
    float4 v0 = __ldcs(&xrow[j + 0]);
    float4 v1 = __ldcs(&xrow[j + 1]);
    float4 v2 = __ldcs(&xrow[j + 2]);
    float4 v3 = __ldcs(&xrow[j + 3]);
    float left  = (j == 0)               ? 0.0f : __ldg(&xs[4u * j - 1]);
    float right = (j + ILP == LEN4)      ? 0.0f : __ldg(&xs[4u * j + 16]);

    // Per-channel taps: uniform within a block -> L1 broadcast
    const float w0 = __ldg(&w[c * 3 + 0]);
    const float w1 = __ldg(&w[c * 3 + 1]);
    const float w2 = __ldg(&w[c * 3 + 2]);
    const float bb = __ldg(&bias[c]);

    // 18-element sliding window: left, v0..v3 (16 elems), right
    float e[18];
    e[0]  = left;
    e[1]  = v0.x; e[2]  = v0.y; e[3]  = v0.z; e[4]  = v0.w;
    e[5]  = v1.x; e[6]  = v1.y; e[7]  = v1.z; e[8]  = v1.w;
    e[9]  = v2.x; e[10] = v2.y; e[11] = v2.z; e[12] = v2.w;
    e[13] = v3.x; e[14] = v3.y; e[15] = v3.z; e[16] = v3.w;
    e[17] = right;

    float4 o[ILP];
#pragma unroll
    for (int q = 0; q < ILP; q++) {
        o[q].x = fmaf(w0, e[4*q + 0], fmaf(w1, e[4*q + 1], fmaf(w2, e[4*q + 2], bb)));
        o[q].y = fmaf(w0, e[4*q + 1], fmaf(w1, e[4*q + 2], fmaf(w2, e[4*q + 3], bb)));
        o[q].z = fmaf(w0, e[4*q + 2], fmaf(w1, e[4*q + 3], fmaf(w2, e[4*q + 4], bb)));
        o[q].w = fmaf(w0, e[4*q + 3], fmaf(w1, e[4*q + 4], fmaf(w2, e[4*q + 5], bb)));
    }

    float4* orow = reinterpret_cast<float4*>(out) + (size_t)row * LEN4;
#pragma unroll
    for (int q = 0; q < ILP; q++)
        __stcs(&orow[j + q], o[q]);
}

extern "C" void kernel_launch(void* const* d_in, const int* in_sizes, int n_in,
                              void* d_out, int out_size)
{
    const float* x    = (const float*)d_in[0];
    const float* w    = (const float*)d_in[1];
    const float* bias = (const float*)d_in[2];
    float* out        = (float*)d_out;

    const unsigned int total_threads = (unsigned int)ROWS * TILES_PER_ROW; // 2,097,152
    const unsigned int blocks = total_threads / NTHREADS;                  // 8192

    dwconv1d_kernel<<<blocks, NTHREADS>>>(x, w, bias, out);
}

// round 3
// speedup vs baseline: 1.1037x; 1.1037x over previous
#include <cuda_runtime.h>

// Depthwise Conv1d: B=32, C=128, L=8192, kernel=3, stride=1, pad=1, fp32.
// out[b,c,l] = w[c,0]*x[b,c,l-1] + w[c,1]*x[b,c,l] + w[c,2]*x[b,c,l+1] + bias[c]
//
// R3: back to R1's fully-coalesced one-float4-per-thread layout, but halo
// elements come from warp shuffles (shfl_up/down of the vector load) instead
// of per-thread scalar LDGs. Only lanes 0/31 of each warp issue a scalar
// halo load (2 per warp vs 64 in R1). Warps never cross a row boundary
// (2048 float4 per row, 32 per warp).

#define BATCH 32
#define CHANS 128
#define LEN   8192
#define LEN4  (LEN / 4)          // 2048 float4 per row
#define ROWS  (BATCH * CHANS)    // 4096
#define NTHREADS 256

__global__ __launch_bounds__(NTHREADS)
void dwconv1d_kernel(const float* __restrict__ x,
                     const float* __restrict__ w,
                     const float* __restrict__ bias,
                     float* __restrict__ out)
{
    unsigned int gid = blockIdx.x * NTHREADS + threadIdx.x;

    unsigned int row  = gid >> 11;        // / LEN4
    unsigned int j    = gid & (LEN4 - 1); // within-row float4 index
    unsigned int c    = row & (CHANS - 1);
    unsigned int lane = threadIdx.x & 31;

    const float4* xrow = reinterpret_cast<const float4*>(x) + (size_t)row * LEN4;
    const float*  xs   = reinterpret_cast<const float*>(xrow);

    float4 v = xrow[j];

    // Per-channel taps: uniform within a block -> L1 broadcast
    const float w0 = __ldg(&w[c * 3 + 0]);
    const float w1 = __ldg(&w[c * 3 + 1]);
    const float w2 = __ldg(&w[c * 3 + 2]);
    const float bb = __ldg(&bias[c]);

    // Halos from neighbor lanes (warp covers 32 consecutive float4s)
    float left  = __shfl_up_sync(0xffffffffu, v.w, 1);
    float right = __shfl_down_sync(0xffffffffu, v.x, 1);
    if (lane == 0)
        left  = (j == 0) ? 0.0f : __ldg(&xs[4u * j - 1]);
    if (lane == 31)
        right = (j == LEN4 - 1) ? 0.0f : __ldg(&xs[4u * j + 4]);

    float4 o;
    o.x = fmaf(w0, left, fmaf(w1, v.x, fmaf(w2, v.y, bb)));
    o.y = fmaf(w0, v.x,  fmaf(w1, v.y, fmaf(w2, v.z, bb)));
    o.z = fmaf(w0, v.y,  fmaf(w1, v.z, fmaf(w2, v.w, bb)));
    o.w = fmaf(w0, v.z,  fmaf(w1, v.w, fmaf(w2, right, bb)));

    reinterpret_cast<float4*>(out)[gid] = o;
}

extern "C" void kernel_launch(void* const* d_in, const int* in_sizes, int n_in,
                              void* d_out, int out_size)
{
    const float* x    = (const float*)d_in[0];
    const float* w    = (const float*)d_in[1];
    const float* bias = (const float*)d_in[2];
    float* out        = (float*)d_out;

    const unsigned int total4 = (unsigned int)ROWS * LEN4; // 8,388,608
    const unsigned int blocks = total4 / NTHREADS;         // 32768

    dwconv1d_kernel<<<blocks, NTHREADS>>>(x, w, bias, out);
}

// round 4
// speedup vs baseline: 1.2141x; 1.1001x over previous
#include <cuda_runtime.h>

// Depthwise Conv1d: B=32, C=128, L=8192, kernel=3, stride=1, pad=1, fp32.
// out[b,c,l] = w[c,0]*x[b,c,l-1] + w[c,1]*x[b,c,l] + w[c,2]*x[b,c,l+1] + bias[c]
//
// R4: R1's coalesced one-float4-per-instruction layout + grid-strided ILP=4.
// Each thread handles 4 float4s spaced gridDim*blockDim apart, so every
// load/store instruction remains perfectly coalesced while per-thread MLP
// rises ~4x (all vector loads front-batched). Halos are scalar L1-hit loads
// as in R1 (fastest variant so far).

#define BATCH 32
#define CHANS 128
#define LEN   8192
#define LEN4  (LEN / 4)          // 2048 float4 per row
#define ROWS  (BATCH * CHANS)    // 4096
#define NTHREADS 256
#define ITER 4
#define TOTAL4   (ROWS * LEN4)            // 8,388,608 float4
#define NTHREADS_TOTAL (TOTAL4 / ITER)    // 2,097,152
#define NBLOCKS  (NTHREADS_TOTAL / NTHREADS) // 8192

__global__ __launch_bounds__(NTHREADS)
void dwconv1d_kernel(const float* __restrict__ x,
                     const float* __restrict__ w,
                     const float* __restrict__ bias,
                     float* __restrict__ out)
{
    const unsigned int gid    = blockIdx.x * NTHREADS + threadIdx.x;
    const unsigned int stride = NTHREADS_TOTAL; // uniform grid stride

    unsigned int idx[ITER], row[ITER], j[ITER], c[ITER];
#pragma unroll
    for (int i = 0; i < ITER; i++) {
        idx[i] = gid + i * stride;
        row[i] = idx[i] >> 11;         // / LEN4
        j[i]   = idx[i] & (LEN4 - 1);  // within-row float4 index
        c[i]   = row[i] & (CHANS - 1);
    }

    // ---- front-batched vector loads (high MLP, fully coalesced) ----
    float4 v[ITER];
#pragma unroll
    for (int i = 0; i < ITER; i++)
        v[i] = reinterpret_cast<const float4*>(x)[idx[i]];

    // ---- halo loads (L1 hits: same/adjacent lines as neighbors' vec loads) ----
    float left[ITER], right[ITER];
#pragma unroll
    for (int i = 0; i < ITER; i++) {
        const float* xs = x + (size_t)row[i] * LEN;
        unsigned int e0 = 4u * j[i];
        left[i]  = (j[i] == 0)        ? 0.0f : __ldg(&xs[e0 - 1]);
        right[i] = (j[i] == LEN4 - 1) ? 0.0f : __ldg(&xs[e0 + 4]);
    }

    // ---- per-channel taps (uniform within warp -> L1 broadcast) ----
    float w0[ITER], w1[ITER], w2[ITER], bb[ITER];
#pragma unroll
    for (int i = 0; i < ITER; i++) {
        w0[i] = __ldg(&w[c[i] * 3 + 0]);
        w1[i] = __ldg(&w[c[i] * 3 + 1]);
        w2[i] = __ldg(&w[c[i] * 3 + 2]);
        bb[i] = __ldg(&bias[c[i]]);
    }

    // ---- compute + store ----
#pragma unroll
    for (int i = 0; i < ITER; i++) {
        float4 o;
        o.x = fmaf(w0[i], left[i], fmaf(w1[i], v[i].x, fmaf(w2[i], v[i].y, bb[i])));
        o.y = fmaf(w0[i], v[i].x,  fmaf(w1[i], v[i].y, fmaf(w2[i], v[i].z, bb[i])));
        o.z = fmaf(w0[i], v[i].y,  fmaf(w1[i], v[i].z, fmaf(w2[i], v[i].w, bb[i])));
        o.w = fmaf(w0[i], v[i].z,  fmaf(w1[i], v[i].w, fmaf(w2[i], right[i], bb[i])));
        reinterpret_cast<float4*>(out)[idx[i]] = o;
    }
}

extern "C" void kernel_launch(void* const* d_in, const int* in_sizes, int n_in,
                              void* d_out, int out_size)
{
    const float* x    = (const float*)d_in[0];
    const float* w    = (const float*)d_in[1];
    const float* bias = (const float*)d_in[2];
    float* out        = (float*)d_out;

    dwconv1d_kernel<<<NBLOCKS, NTHREADS>>>(x, w, bias, out);
}